// round 15
// baseline (speedup 1.0000x reference)
#include <cuda_runtime.h>
#include <math_constants.h>

#define NROWS 8192
#define DIM   64
#define KNN   32
#define MOUT  (NROWS - KNN)      // 8160 query rows
#define QT    16                 // queries per block (4 per warp)
#define CT    128                // candidate tile rows
#define PS    66                 // float2 stride per pair-row (66*2=132 ≡ 4 mod 32 banks)
#define NT_SEL 128               // select block size (4 warps)

__device__ float g_sq[NROWS];

typedef unsigned long long u64t;

__device__ __forceinline__ void ffma2(u64t& acc, u64t a, u64t b) {
    asm("fma.rn.f32x2 %0, %1, %2, %0;" : "+l"(acc) : "l"(a), "l"(b));
}
__device__ __forceinline__ float2 unpack2(u64t v) {
    float2 r;
    r.x = __uint_as_float((unsigned)v);
    r.y = __uint_as_float((unsigned)(v >> 32));
    return r;
}

__global__ void sq_kernel(const float* __restrict__ X) {
    int i = blockIdx.x * blockDim.x + threadIdx.x;
    if (i < NROWS) {
        const float4* x4 = (const float4*)(X + (size_t)i * DIM);
        float s = 0.f;
        #pragma unroll
        for (int t = 0; t < DIM / 4; ++t) {
            float4 v = x4[t];
            s += v.x * v.x + v.y * v.y + v.z * v.z + v.w * v.w;
        }
        g_sq[i] = s;
    }
}

// ascending full bitonic sort of (d,i) across 32 lanes, lex order
__device__ __forceinline__ void bsort32(float& d, int& i, int lane) {
    #pragma unroll
    for (int k = 2; k <= 32; k <<= 1) {
        #pragma unroll
        for (int s = k >> 1; s > 0; s >>= 1) {
            float od = __shfl_xor_sync(0xffffffffu, d, s);
            int   oi = __shfl_xor_sync(0xffffffffu, i, s);
            bool up    = ((lane & k) == 0);
            bool lower = ((lane & s) == 0);
            bool mlt   = (d < od) || (d == od && i < oi);
            bool take  = (lower == up) ? !mlt : mlt;
            if (take) { d = od; i = oi; }
        }
    }
}

// ascending cleanup of a bitonic 32-sequence
__device__ __forceinline__ void bmerge32(float& d, int& i, int lane) {
    #pragma unroll
    for (int s = 16; s > 0; s >>= 1) {
        float od = __shfl_xor_sync(0xffffffffu, d, s);
        int   oi = __shfl_xor_sync(0xffffffffu, i, s);
        bool lower = ((lane & s) == 0);
        bool mlt   = (d < od) || (d == od && i < oi);
        bool take  = lower ? !mlt : mlt;
        if (take) { d = od; i = oi; }
    }
}

// reference-rounding tree sum-of-squares; reads dim t from f2[t].x
__device__ __forceinline__ float sq_tree_f2(const float2* __restrict__ c) {
    float t[32];
    #pragma unroll
    for (int l = 0; l < 32; ++l)
        t[l] = __fadd_rn(__fmul_rn(c[l].x, c[l].x), __fmul_rn(c[l + 32].x, c[l + 32].x));
    #pragma unroll
    for (int l = 0; l < 16; ++l) t[l] = __fadd_rn(t[l], t[l + 16]);
    #pragma unroll
    for (int l = 0; l < 8; ++l)  t[l] = __fadd_rn(t[l], t[l + 8]);
    #pragma unroll
    for (int l = 0; l < 4; ++l)  t[l] = __fadd_rn(t[l], t[l + 4]);
    t[0] = __fadd_rn(t[0], t[2]);
    t[1] = __fadd_rn(t[1], t[3]);
    return __fadd_rn(t[0], t[1]);
}
__device__ __forceinline__ float sq_tree_arr(const float* __restrict__ c) {
    float t[32];
    #pragma unroll
    for (int l = 0; l < 32; ++l)
        t[l] = __fadd_rn(__fmul_rn(c[l], c[l]), __fmul_rn(c[l + 32], c[l + 32]));
    #pragma unroll
    for (int l = 0; l < 16; ++l) t[l] = __fadd_rn(t[l], t[l + 16]);
    #pragma unroll
    for (int l = 0; l < 8; ++l)  t[l] = __fadd_rn(t[l], t[l + 8]);
    #pragma unroll
    for (int l = 0; l < 4; ++l)  t[l] = __fadd_rn(t[l], t[l + 4]);
    t[0] = __fadd_rn(t[0], t[2]);
    t[1] = __fadd_rn(t[1], t[3]);
    return __fadd_rn(t[0], t[1]);
}

// ------------- fused: packed-f32x2 selection + reference-rounding refine -------------
__global__ __launch_bounds__(NT_SEL, 3) void knn_fused_kernel(const float* __restrict__ X,
                                                              void* __restrict__ out, int mode) {
    // candidate tile, pair-interleaved: xsP[p*PS + d] = (x[r][d], x[r+32][d]),
    //   r = (p<32) ? p : p+32  (p 0..63 covers rows 0..127 of the tile)
    __shared__ float2 xsP[64 * PS];
    __shared__ float2 qsP[QT * DIM];   // duplicated queries: (q_d, q_d)
    __shared__ float  sqc[CT];

    const int tid  = threadIdx.x;
    const int lane = tid & 31;
    const int warp = tid >> 5;
    const int b  = gridDim.x - 1 - blockIdx.x;
    const int qb = KNN + b * QT;

    const float4* X4 = (const float4*)X;

    // stage duplicated queries
    for (int u = tid; u < QT * (DIM / 4); u += NT_SEL) {
        int q = u >> 4, c = u & 15;
        float4 v = X4[(size_t)(qb + q) * (DIM / 4) + c];
        *(float4*)&qsP[q * DIM + 4 * c]     = make_float4(v.x, v.x, v.y, v.y);
        *(float4*)&qsP[q * DIM + 4 * c + 2] = make_float4(v.z, v.z, v.w, v.w);
    }

    float sqq[4];
    float ld[4], kd[4];
    int   li[4], ki[4];
    #pragma unroll
    for (int w = 0; w < 4; ++w) {
        sqq[w] = g_sq[qb + warp * 4 + w];
        ld[w]  = CUDART_INF_F;  kd[w] = CUDART_INF_F;
        li[w]  = -1;            ki[w] = 0x7fffffff;
    }

    const int cand_end = qb + QT;
    for (int tb = 0; tb < cand_end; tb += CT) {
        __syncthreads();
        // stage candidate tile pair-interleaved (rows tb+r, tb+r+32 per pair-row)
        for (int u = tid; u < 64 * (DIM / 4); u += NT_SEL) {
            int p = u & 63, c = u >> 6;
            int r = (p < 32) ? p : p + 32;
            float4 a  = X4[(size_t)(tb + r) * (DIM / 4) + c];
            float4 bv = X4[(size_t)(tb + r + 32) * (DIM / 4) + c];
            *(float4*)&xsP[p * PS + 4 * c]     = make_float4(a.x, bv.x, a.y, bv.y);
            *(float4*)&xsP[p * PS + 4 * c + 2] = make_float4(a.z, bv.z, a.w, bv.w);
        }
        if (tid < CT) sqc[tid] = g_sq[tb + tid];
        __syncthreads();

        // packed dual-FMA mainloop: accA = cands (lane, lane+32), accB = (lane+64, lane+96)
        u64t accA[4], accB[4];
        #pragma unroll
        for (int w = 0; w < 4; ++w) { accA[w] = 0ull; accB[w] = 0ull; }

        const float2* xrow0 = &xsP[lane * PS];
        const float2* xrow1 = &xsP[(lane + 32) * PS];

        #pragma unroll 8
        for (int d = 0; d < DIM; d += 2) {
            ulonglong2 cA = *(const ulonglong2*)&xrow0[d];
            ulonglong2 cB = *(const ulonglong2*)&xrow1[d];
            #pragma unroll
            for (int w = 0; w < 4; ++w) {
                ulonglong2 qq = *(const ulonglong2*)&qsP[(warp * 4 + w) * DIM + d];
                ffma2(accA[w], qq.x, cA.x);
                ffma2(accB[w], qq.x, cB.x);
                ffma2(accA[w], qq.y, cA.y);
                ffma2(accB[w], qq.y, cB.y);
            }
        }

        float acc[4][4];
        #pragma unroll
        for (int w = 0; w < 4; ++w) {
            float2 a = unpack2(accA[w]);
            float2 c2 = unpack2(accB[w]);
            acc[w][0] = a.x;  acc[w][1] = a.y;
            acc[w][2] = c2.x; acc[w][3] = c2.y;
        }

        // selection (identical to R14)
        #pragma unroll
        for (int ch = 0; ch < 4; ++ch) {
            const int   j  = tb + ch * 32 + lane;
            const float sc = sqc[ch * 32 + lane];
            #pragma unroll
            for (int w = 0; w < 4; ++w) {
                const int r = qb + warp * 4 + w;
                float dist = (j < r) ? fmaxf(sqq[w] + sc - 2.f * acc[w][ch], 0.f)
                                     : CUDART_INF_F;

                if (tb == 0 && ch == 0) {
                    float d0 = dist; int i0 = j;
                    bsort32(d0, i0, lane);
                    ld[w] = d0; li[w] = i0;
                    kd[w] = __shfl_sync(0xffffffffu, d0, 31);
                    ki[w] = __shfl_sync(0xffffffffu, i0, 31);
                    continue;
                }

                unsigned hits = __ballot_sync(0xffffffffu,
                                              dist < kd[w] || (dist == kd[w] && j < ki[w]));
                if (!hits) continue;
                int nh = __popc(hits);

                if (nh >= 8) {
                    bool ishit = (hits >> lane) & 1u;
                    float hd = ishit ? dist : CUDART_INF_F;
                    int   hi = ishit ? j    : 0x7fffffff;
                    bsort32(hd, hi, lane);
                    float rd = __shfl_xor_sync(0xffffffffu, hd, 31);
                    int   ri = __shfl_xor_sync(0xffffffffu, hi, 31);
                    bool keep = (ld[w] < rd) || (ld[w] == rd && li[w] < ri);
                    float nd = keep ? ld[w] : rd;
                    int   ni = keep ? li[w] : ri;
                    bmerge32(nd, ni, lane);
                    ld[w] = nd; li[w] = ni;
                } else {
                    while (hits) {
                        int src = __ffs(hits) - 1;
                        hits &= hits - 1;
                        float dv = __shfl_sync(0xffffffffu, dist, src);
                        int   iv = tb + ch * 32 + src;
                        bool lt  = (ld[w] < dv) || (ld[w] == dv && li[w] < iv);
                        int  pos = __popc(__ballot_sync(0xffffffffu, lt));
                        if (pos < 32) {
                            float pd = __shfl_up_sync(0xffffffffu, ld[w], 1);
                            int   pi = __shfl_up_sync(0xffffffffu, li[w], 1);
                            if (lane == pos)      { ld[w] = dv; li[w] = iv; }
                            else if (lane > pos)  { ld[w] = pd; li[w] = pi; }
                        }
                    }
                }
                kd[w] = __shfl_sync(0xffffffffu, ld[w], 31);
                ki[w] = __shfl_sync(0xffffffffu, li[w], 31);
            }
        }
    }

    // ---------------- phase 2: refine epilogue (identical math) ----------------
    #pragma unroll
    for (int w = 0; w < 4; ++w) {
        const float2* qrow = &qsP[(warp * 4 + w) * DIM];
        float sqr = sq_tree_f2(qrow);

        int jj = li[w];

        float cv[DIM];
        const float4* crow = X4 + (size_t)jj * (DIM / 4);
        #pragma unroll
        for (int t = 0; t < DIM / 4; ++t) {
            float4 v = __ldg(&crow[t]);
            cv[4 * t + 0] = v.x; cv[4 * t + 1] = v.y;
            cv[4 * t + 2] = v.z; cv[4 * t + 3] = v.w;
        }
        float sqj = sq_tree_arr(cv);

        float dot = 0.f;
        #pragma unroll
        for (int t = 0; t < DIM; ++t) dot = __fmaf_rn(qrow[t].x, cv[t], dot);

        float df = fmaxf(__fsub_rn(__fadd_rn(sqr, sqj), __fmul_rn(2.f, dot)), 0.f);

        bsort32(df, jj, lane);

        const size_t m = (size_t)(qb + warp * 4 + w - KNN);
        float* of = (float*)out;
        of[m * KNN + lane] = df;
        if (mode == 0) {
            of[(size_t)MOUT * KNN + m * KNN + lane] = (float)jj;
        } else if (mode == 2) {
            long long* oi = (long long*)((char*)out + (size_t)MOUT * KNN * sizeof(float));
            oi[m * KNN + lane] = (long long)jj;
        }
    }
}

extern "C" void kernel_launch(void* const* d_in, const int* in_sizes, int n_in,
                              void* d_out, int out_size) {
    const float* X = (const float*)d_in[0];
    for (int i = 0; i < n_in; ++i) {
        if (in_sizes[i] == NROWS * DIM) { X = (const float*)d_in[i]; break; }
    }

    sq_kernel<<<NROWS / 256, 256>>>(X);

    const int MK = MOUT * KNN;
    int mode;
    if (out_size == MK)            mode = 1;
    else if (out_size == 2 * MK)   mode = 0;
    else                           mode = 2;
    knn_fused_kernel<<<MOUT / QT, NT_SEL>>>(X, d_out, mode);
}